// round 1
// baseline (speedup 1.0000x reference)
#include <cuda_runtime.h>
#include <math.h>

#define BB     32
#define HH     16
#define DD     256
#define RDIM   64
#define NEMB   4096
#define NINT   16384
#define NSLOTS 32768
#define KVLEN  1024

// ---------------- scratch (static device globals; no allocation) ----------------
__device__ float g_h[BB * NEMB];        // layernorm output
__device__ float g_q[BB * NEMB];
__device__ float g_k[BB * NEMB];
__device__ float g_v[BB * NEMB];
__device__ float g_ctx[BB * NEMB];      // attention context
__device__ float g_attn[BB * NEMB];     // ctx @ wo
__device__ float g_mact[BB * NINT];     // gelu(fc_in)
__device__ float g_part[8 * 1024 * 1024];  // split-K partials (max 16*32*16384)
__device__ int   g_kmap[NSLOTS];
__device__ int   g_vmap[NSLOTS];

// ---------------- layernorm ----------------
__global__ void ln_kernel(const float* __restrict__ x, const float* __restrict__ w,
                          const float* __restrict__ bias) {
    int b = blockIdx.x, tid = threadIdx.x;
    const float* row = x + b * NEMB;
    float s = 0.f, s2 = 0.f;
    for (int i = tid; i < NEMB; i += 256) { float v = row[i]; s += v; s2 += v * v; }
    __shared__ float r1[256], r2[256];
    r1[tid] = s; r2[tid] = s2;
    __syncthreads();
    for (int off = 128; off; off >>= 1) {
        if (tid < off) { r1[tid] += r1[tid + off]; r2[tid] += r2[tid + off]; }
        __syncthreads();
    }
    float mean = r1[0] * (1.f / NEMB);
    float var  = r2[0] * (1.f / NEMB) - mean * mean;
    float inv  = rsqrtf(var + 1e-5f);
    for (int i = tid; i < NEMB; i += 256)
        g_h[b * NEMB + i] = (row[i] - mean) * inv * w[i] + bias[i];
}

// ---------------- skinny GEMM: C[32,N] = A[32,K] @ W[K,N], split-K partials ----------------
// grid: (N/512, S).  block: 128 threads, each owns 4 columns x 32 batches.
__global__ void gemm_kernel(const float* __restrict__ A, const float* __restrict__ W,
                            float* __restrict__ part, int K, int N, int chunk) {
    __shared__ float a_s[128][BB + 1];
    const int tid = threadIdx.x;
    const int n0  = blockIdx.x * 512 + tid * 4;
    const int s   = blockIdx.y;
    const int k0  = s * chunk;

    float4 acc[BB];
#pragma unroll
    for (int b = 0; b < BB; ++b) acc[b] = make_float4(0.f, 0.f, 0.f, 0.f);

    for (int kc = 0; kc < chunk; kc += 128) {
        __syncthreads();
#pragma unroll
        for (int idx = tid; idx < 128 * BB; idx += 128) {
            int kk = idx & 127;     // = tid  -> coalesced over k
            int b  = idx >> 7;      // fixed per iteration
            a_s[kk][b] = A[(size_t)b * K + (k0 + kc + kk)];
        }
        __syncthreads();
#pragma unroll 4
        for (int kk = 0; kk < 128; ++kk) {
            const float4 w4 = *reinterpret_cast<const float4*>(W + (size_t)(k0 + kc + kk) * N + n0);
#pragma unroll
            for (int b = 0; b < BB; ++b) {
                float a = a_s[kk][b];
                acc[b].x = fmaf(a, w4.x, acc[b].x);
                acc[b].y = fmaf(a, w4.y, acc[b].y);
                acc[b].z = fmaf(a, w4.z, acc[b].z);
                acc[b].w = fmaf(a, w4.w, acc[b].w);
            }
        }
    }
#pragma unroll
    for (int b = 0; b < BB; ++b)
        *reinterpret_cast<float4*>(part + ((size_t)s * BB + b) * N + n0) = acc[b];
}

// ---------------- split-K reductions with fused epilogues ----------------
__global__ void reduce_plain(const float* __restrict__ part, float* __restrict__ out,
                             int N, int S) {
    int idx = blockIdx.x * 256 + threadIdx.x;
    float s = 0.f;
    for (int j = 0; j < S; ++j) s += part[(size_t)j * BB * N + idx];
    out[idx] = s;
}

__global__ void reduce_bias_gelu(const float* __restrict__ part, const float* __restrict__ bias,
                                 float* __restrict__ out, int N, int S) {
    int idx = blockIdx.x * 256 + threadIdx.x;
    float s = bias[idx & (N - 1)];
    for (int j = 0; j < S; ++j) s += part[(size_t)j * BB * N + idx];
    float x = s;
    float t = tanhf(0.7978845608028654f * (x + 0.044715f * x * x * x));
    out[idx] = 0.5f * x * (1.f + t);
}

__global__ void reduce_final(const float* __restrict__ part, const float* __restrict__ bias,
                             const float* __restrict__ attn, const float* __restrict__ resid,
                             float* __restrict__ out, int N, int S) {
    int idx = blockIdx.x * 256 + threadIdx.x;
    float s = 0.f;
    for (int j = 0; j < S; ++j) s += part[(size_t)j * BB * N + idx];
    out[idx] = s + bias[idx & (N - 1)] + attn[idx] + resid[idx];
}

// ---------------- slot maps + rope ----------------
__global__ void init_maps_kernel() {
    int i = blockIdx.x * 256 + threadIdx.x;
    if (i < NSLOTS) { g_kmap[i] = -1; g_vmap[i] = -1; }
}

__global__ void rope_kernel(const int* __restrict__ nkl, const int* __restrict__ nvl,
                            const int* __restrict__ pos) {
    int bh = blockIdx.x;
    int b = bh >> 4, h = bh & 15;
    int m = threadIdx.x;  // 0..31 rotary pairs
    if (h == 0 && m == 0) { g_kmap[nkl[b]] = b; g_vmap[nvl[b]] = b; }
    double inv_freq = pow(10000.0, -(double)(2 * m) / (double)RDIM);
    double ang = (double)pos[b] * inv_freq;
    float sn = (float)sin(ang), cs = (float)cos(ang);
    int base = b * NEMB + h * DD;
    float x1 = g_q[base + 2 * m], x2 = g_q[base + 2 * m + 1];
    g_q[base + 2 * m]     = x1 * cs - x2 * sn;
    g_q[base + 2 * m + 1] = x2 * cs + x1 * sn;
    x1 = g_k[base + 2 * m]; x2 = g_k[base + 2 * m + 1];
    g_k[base + 2 * m]     = x1 * cs - x2 * sn;
    g_k[base + 2 * m + 1] = x2 * cs + x1 * sn;
}

// ---------------- attention: one block per (h, b) ----------------
__global__ void attn_kernel(const float* __restrict__ kcache, const float* __restrict__ vcache,
                            const int* __restrict__ kidx, const int* __restrict__ vidx,
                            const float* __restrict__ mask, float* __restrict__ ctx) {
    const int h = blockIdx.x, b = blockIdx.y;
    const int tid = threadIdx.x, lane = tid & 31, warp = tid >> 5;
    __shared__ const float* kptr[KVLEN];
    __shared__ const float* vptr[KVLEN];
    __shared__ float sc[KVLEN];
    __shared__ float qs[DD];
    __shared__ float red[8];

    // precompute gather row pointers (resolves new-token overwrite virtually)
    for (int l = tid; l < KVLEN; l += 256) {
        int ki = kidx[b * KVLEN + l];
        int mk = g_kmap[ki];
        kptr[l] = (mk >= 0) ? (g_k + mk * NEMB + h * DD)
                            : (kcache + (size_t)ki * NEMB + h * DD);
        int vi = vidx[b * KVLEN + l];
        int mv = g_vmap[vi];
        vptr[l] = (mv >= 0) ? (g_v + mv * NEMB + h * DD)
                            : (vcache + (size_t)vi * NEMB + h * DD);
    }
    qs[tid] = g_q[b * NEMB + h * DD + tid];
    __syncthreads();

    // pass 1: scores, warp per row, 4 rows in flight
    const float4* qp = reinterpret_cast<const float4*>(qs);
    float4 qa = qp[lane], qb = qp[32 + lane];
    const float* mrow = mask + b * KVLEN;
    for (int l0 = warp * 128; l0 < warp * 128 + 128; l0 += 4) {
        float dot[4];
#pragma unroll
        for (int u = 0; u < 4; ++u) {
            const float4* kr = reinterpret_cast<const float4*>(kptr[l0 + u]);
            float4 ka = kr[lane], kb = kr[32 + lane];
            dot[u] = qa.x * ka.x + qa.y * ka.y + qa.z * ka.z + qa.w * ka.w
                   + qb.x * kb.x + qb.y * kb.y + qb.z * kb.z + qb.w * kb.w;
        }
#pragma unroll
        for (int u = 0; u < 4; ++u) {
#pragma unroll
            for (int off = 16; off; off >>= 1)
                dot[u] += __shfl_xor_sync(0xffffffffu, dot[u], off);
        }
        if (lane == 0) {
#pragma unroll
            for (int u = 0; u < 4; ++u)
                sc[l0 + u] = dot[u] * 0.0625f + mrow[l0 + u];
        }
    }
    __syncthreads();

    // softmax over 1024
    float lm = -1e30f;
    for (int l = tid; l < KVLEN; l += 256) lm = fmaxf(lm, sc[l]);
#pragma unroll
    for (int off = 16; off; off >>= 1) lm = fmaxf(lm, __shfl_xor_sync(0xffffffffu, lm, off));
    if (lane == 0) red[warp] = lm;
    __syncthreads();
    float gm = red[0];
#pragma unroll
    for (int w = 1; w < 8; ++w) gm = fmaxf(gm, red[w]);
    float ls = 0.f;
    for (int l = tid; l < KVLEN; l += 256) {
        float e = __expf(sc[l] - gm);
        sc[l] = e;
        ls += e;
    }
#pragma unroll
    for (int off = 16; off; off >>= 1) ls += __shfl_xor_sync(0xffffffffu, ls, off);
    __syncthreads();
    if (lane == 0) red[warp] = ls;
    __syncthreads();
    float tot = red[0];
#pragma unroll
    for (int w = 1; w < 8; ++w) tot += red[w];
    float inv = 1.f / tot;

    // pass 2: ctx, thread per dim
    float acc = 0.f;
#pragma unroll 8
    for (int l = 0; l < KVLEN; ++l)
        acc = fmaf(sc[l], vptr[l][tid], acc);
    ctx[b * NEMB + h * DD + tid] = acc * inv;
}

// ---------------- launch ----------------
extern "C" void kernel_launch(void* const* d_in, const int* in_sizes, int n_in,
                              void* d_out, int out_size) {
    const float* hs  = (const float*)d_in[0];
    const float* kc  = (const float*)d_in[1];
    const float* vc  = (const float*)d_in[2];
    const float* lnw = (const float*)d_in[3];
    const float* lnb = (const float*)d_in[4];
    const float* wq  = (const float*)d_in[5];
    const float* wk  = (const float*)d_in[6];
    const float* wv  = (const float*)d_in[7];
    const float* wo  = (const float*)d_in[8];
    const float* fiw = (const float*)d_in[9];
    const float* fib = (const float*)d_in[10];
    const float* fow = (const float*)d_in[11];
    const float* fob = (const float*)d_in[12];
    const float* msk = (const float*)d_in[13];
    const int* nkl   = (const int*)d_in[14];
    const int* nvl   = (const int*)d_in[15];
    const int* pki   = (const int*)d_in[16];
    const int* pvi   = (const int*)d_in[17];
    const int* pos   = (const int*)d_in[18];
    float* out = (float*)d_out;

    float *ph, *pq, *pk, *pv, *pctx, *pattn, *pm, *ppart;
    cudaGetSymbolAddress((void**)&ph,    g_h);
    cudaGetSymbolAddress((void**)&pq,    g_q);
    cudaGetSymbolAddress((void**)&pk,    g_k);
    cudaGetSymbolAddress((void**)&pv,    g_v);
    cudaGetSymbolAddress((void**)&pctx,  g_ctx);
    cudaGetSymbolAddress((void**)&pattn, g_attn);
    cudaGetSymbolAddress((void**)&pm,    g_mact);
    cudaGetSymbolAddress((void**)&ppart, g_part);

    ln_kernel<<<BB, 256>>>(hs, lnw, lnb);
    init_maps_kernel<<<NSLOTS / 256, 256>>>();

    // q, k, v  (K=4096, N=4096, S=32, chunk=128)
    gemm_kernel<<<dim3(NEMB / 512, 32), 128>>>(ph, wq, ppart, NEMB, NEMB, 128);
    reduce_plain<<<BB * NEMB / 256, 256>>>(ppart, pq, NEMB, 32);
    gemm_kernel<<<dim3(NEMB / 512, 32), 128>>>(ph, wk, ppart, NEMB, NEMB, 128);
    reduce_plain<<<BB * NEMB / 256, 256>>>(ppart, pk, NEMB, 32);
    gemm_kernel<<<dim3(NEMB / 512, 32), 128>>>(ph, wv, ppart, NEMB, NEMB, 128);
    reduce_plain<<<BB * NEMB / 256, 256>>>(ppart, pv, NEMB, 32);

    rope_kernel<<<BB * HH, 32>>>(nkl, nvl, pos);

    attn_kernel<<<dim3(HH, BB), 256>>>(kc, vc, pki, pvi, msk, pctx);

    // wo
    gemm_kernel<<<dim3(NEMB / 512, 32), 128>>>(pctx, wo, ppart, NEMB, NEMB, 128);
    reduce_plain<<<BB * NEMB / 256, 256>>>(ppart, pattn, NEMB, 32);

    // fc_in + gelu  (K=4096, N=16384, S=16, chunk=256)
    gemm_kernel<<<dim3(NINT / 512, 16), 128>>>(ph, fiw, ppart, NEMB, NINT, 256);
    reduce_bias_gelu<<<BB * NINT / 256, 256>>>(ppart, fib, pm, NINT, 16);

    // fc_out + bias + attn + residual  (K=16384, N=4096, S=32, chunk=512)
    gemm_kernel<<<dim3(NEMB / 512, 32), 128>>>(pm, fow, ppart, NINT, NEMB, 512);
    reduce_final<<<BB * NEMB / 256, 256>>>(ppart, fob, pattn, hs, out, NEMB, 32);
}

// round 16
// speedup vs baseline: 1.0323x; 1.0323x over previous
#include <cuda_runtime.h>
#include <math.h>

#define BB     32
#define HH     16
#define DD     256
#define RDIM   64
#define NEMB   4096
#define NINT   16384
#define NSLOTS 32768
#define KVLEN  1024

typedef unsigned long long u64;

__device__ __forceinline__ u64 pack2(float lo, float hi) {
    u64 r; asm("mov.b64 %0,{%1,%2};" : "=l"(r) : "f"(lo), "f"(hi)); return r;
}
__device__ __forceinline__ u64 fma2(u64 a, u64 b, u64 c) {
    u64 d; asm("fma.rn.f32x2 %0,%1,%2,%3;" : "=l"(d) : "l"(a), "l"(b), "l"(c)); return d;
}

// ---------------- scratch (static device globals; no allocation) ----------------
__device__ float g_h[BB * NEMB];        // layernorm output
__device__ float g_q[BB * NEMB];
__device__ float g_k[BB * NEMB];
__device__ float g_v[BB * NEMB];
__device__ float g_ctx[BB * NEMB];      // attention context
__device__ float g_attn[BB * NEMB];     // ctx @ wo
__device__ float g_mact[BB * NINT];     // gelu(fc_in)
__device__ float g_part[13 * 1024 * 1024]; // split-K partials (qkv: 3*32*32*4096 = 12.6M)
__device__ int   g_kmap[NSLOTS];
__device__ int   g_vmap[NSLOTS];

#define QKV_PART_STRIDE ((size_t)32 * BB * NEMB)   // per-matrix partials region

// ---------------- layernorm ----------------
__global__ void ln_kernel(const float* __restrict__ x, const float* __restrict__ w,
                          const float* __restrict__ bias) {
    int b = blockIdx.x, tid = threadIdx.x;
    const float* row = x + b * NEMB;
    float s = 0.f, s2 = 0.f;
    for (int i = tid; i < NEMB; i += 256) { float v = row[i]; s += v; s2 += v * v; }
    __shared__ float r1[256], r2[256];
    r1[tid] = s; r2[tid] = s2;
    __syncthreads();
    for (int off = 128; off; off >>= 1) {
        if (tid < off) { r1[tid] += r1[tid + off]; r2[tid] += r2[tid + off]; }
        __syncthreads();
    }
    float mean = r1[0] * (1.f / NEMB);
    float var  = r2[0] * (1.f / NEMB) - mean * mean;
    float inv  = rsqrtf(var + 1e-5f);
    for (int i = tid; i < NEMB; i += 256)
        g_h[b * NEMB + i] = (row[i] - mean) * inv * w[i] + bias[i];
}

// ---------------- skinny GEMM core (f32x2 packed FMA) ----------------
__device__ __forceinline__ void gemm_body(
        const float* __restrict__ A, const float* __restrict__ W,
        float* __restrict__ part, int K, int N, int chunk,
        int n0, int s, int tid, float a_s[128][BB + 1]) {
    const int k0 = s * chunk;
    u64 acc[BB][2];
#pragma unroll
    for (int b = 0; b < BB; ++b) { acc[b][0] = 0ull; acc[b][1] = 0ull; }

    for (int kc = 0; kc < chunk; kc += 128) {
        __syncthreads();
#pragma unroll
        for (int idx = tid; idx < 128 * BB; idx += 128) {
            int kk = idx & 127;
            int b  = idx >> 7;
            a_s[kk][b] = A[(size_t)b * K + (k0 + kc + kk)];
        }
        __syncthreads();
#pragma unroll 4
        for (int kk = 0; kk < 128; ++kk) {
            const ulonglong2 w2 = *reinterpret_cast<const ulonglong2*>(
                W + (size_t)(k0 + kc + kk) * N + n0);
#pragma unroll
            for (int b = 0; b < BB; ++b) {
                float a = a_s[kk][b];
                u64 ap = pack2(a, a);
                acc[b][0] = fma2(ap, w2.x, acc[b][0]);
                acc[b][1] = fma2(ap, w2.y, acc[b][1]);
            }
        }
    }
#pragma unroll
    for (int b = 0; b < BB; ++b) {
        ulonglong2 o; o.x = acc[b][0]; o.y = acc[b][1];
        *reinterpret_cast<ulonglong2*>(part + ((size_t)s * BB + b) * N + n0) = o;
    }
}

// grid: (N/512, S). 128 threads.
__global__ void __launch_bounds__(128) gemm_kernel(
        const float* __restrict__ A, const float* __restrict__ W,
        float* __restrict__ part, int K, int N, int chunk) {
    __shared__ float a_s[128][BB + 1];
    gemm_body(A, W, part, K, N, chunk,
              blockIdx.x * 512 + threadIdx.x * 4, blockIdx.y, threadIdx.x, a_s);
}

// fused QKV: grid (NEMB/512, S, 3); z selects weight + partials region.
__global__ void __launch_bounds__(128) gemm_qkv_kernel(
        const float* __restrict__ A,
        const float* __restrict__ wq, const float* __restrict__ wk,
        const float* __restrict__ wv, float* __restrict__ part, int chunk) {
    __shared__ float a_s[128][BB + 1];
    const float* W = (blockIdx.z == 0) ? wq : (blockIdx.z == 1) ? wk : wv;
    gemm_body(A, W, part + blockIdx.z * QKV_PART_STRIDE, NEMB, NEMB, chunk,
              blockIdx.x * 512 + threadIdx.x * 4, blockIdx.y, threadIdx.x, a_s);
}

// ---------------- split-K reductions, float4-vectorized, fused epilogues ----------------
__global__ void reduce_plain(const float* __restrict__ part, float* __restrict__ out,
                             int N, int S) {
    int base = (blockIdx.x * 256 + threadIdx.x) * 4;
    float4 s = make_float4(0.f, 0.f, 0.f, 0.f);
    for (int j = 0; j < S; ++j) {
        float4 p = *reinterpret_cast<const float4*>(part + (size_t)j * BB * N + base);
        s.x += p.x; s.y += p.y; s.z += p.z; s.w += p.w;
    }
    *reinterpret_cast<float4*>(out + base) = s;
}

// fused QKV reduce: grid (BB*NEMB/1024, 3)
__global__ void reduce_qkv(const float* __restrict__ part,
                           float* __restrict__ oq, float* __restrict__ ok,
                           float* __restrict__ ov) {
    int base = (blockIdx.x * 256 + threadIdx.x) * 4;
    const float* p0 = part + blockIdx.y * QKV_PART_STRIDE;
    float4 s = make_float4(0.f, 0.f, 0.f, 0.f);
    for (int j = 0; j < 32; ++j) {
        float4 p = *reinterpret_cast<const float4*>(p0 + (size_t)j * BB * NEMB + base);
        s.x += p.x; s.y += p.y; s.z += p.z; s.w += p.w;
    }
    float* out = (blockIdx.y == 0) ? oq : (blockIdx.y == 1) ? ok : ov;
    *reinterpret_cast<float4*>(out + base) = s;
}

__device__ __forceinline__ float gelu1(float x) {
    float t = tanhf(0.7978845608028654f * (x + 0.044715f * x * x * x));
    return 0.5f * x * (1.f + t);
}

__global__ void reduce_bias_gelu(const float* __restrict__ part, const float* __restrict__ bias,
                                 float* __restrict__ out, int N, int S) {
    int base = (blockIdx.x * 256 + threadIdx.x) * 4;
    float4 s = *reinterpret_cast<const float4*>(bias + (base & (N - 1)));
    for (int j = 0; j < S; ++j) {
        float4 p = *reinterpret_cast<const float4*>(part + (size_t)j * BB * N + base);
        s.x += p.x; s.y += p.y; s.z += p.z; s.w += p.w;
    }
    float4 o;
    o.x = gelu1(s.x); o.y = gelu1(s.y); o.z = gelu1(s.z); o.w = gelu1(s.w);
    *reinterpret_cast<float4*>(out + base) = o;
}

__global__ void reduce_final(const float* __restrict__ part, const float* __restrict__ bias,
                             const float* __restrict__ attn, const float* __restrict__ resid,
                             float* __restrict__ out, int N, int S) {
    int base = (blockIdx.x * 256 + threadIdx.x) * 4;
    float4 s = make_float4(0.f, 0.f, 0.f, 0.f);
    for (int j = 0; j < S; ++j) {
        float4 p = *reinterpret_cast<const float4*>(part + (size_t)j * BB * N + base);
        s.x += p.x; s.y += p.y; s.z += p.z; s.w += p.w;
    }
    float4 bi = *reinterpret_cast<const float4*>(bias + (base & (N - 1)));
    float4 at = *reinterpret_cast<const float4*>(attn + base);
    float4 re = *reinterpret_cast<const float4*>(resid + base);
    float4 o;
    o.x = s.x + bi.x + at.x + re.x;
    o.y = s.y + bi.y + at.y + re.y;
    o.z = s.z + bi.z + at.z + re.z;
    o.w = s.w + bi.w + at.w + re.w;
    *reinterpret_cast<float4*>(out + base) = o;
}

// ---------------- slot maps + rope ----------------
__global__ void init_maps_kernel() {
    int i = blockIdx.x * 256 + threadIdx.x;
    if (i < NSLOTS) { g_kmap[i] = -1; g_vmap[i] = -1; }
}

__global__ void rope_kernel(const int* __restrict__ nkl, const int* __restrict__ nvl,
                            const int* __restrict__ pos) {
    int bh = blockIdx.x;
    int b = bh >> 4, h = bh & 15;
    int m = threadIdx.x;  // 0..31 rotary pairs
    if (h == 0 && m == 0) { g_kmap[nkl[b]] = b; g_vmap[nvl[b]] = b; }
    double inv_freq = pow(10000.0, -(double)(2 * m) / (double)RDIM);
    double ang = (double)pos[b] * inv_freq;
    float sn = (float)sin(ang), cs = (float)cos(ang);
    int base = b * NEMB + h * DD;
    float x1 = g_q[base + 2 * m], x2 = g_q[base + 2 * m + 1];
    g_q[base + 2 * m]     = x1 * cs - x2 * sn;
    g_q[base + 2 * m + 1] = x2 * cs + x1 * sn;
    x1 = g_k[base + 2 * m]; x2 = g_k[base + 2 * m + 1];
    g_k[base + 2 * m]     = x1 * cs - x2 * sn;
    g_k[base + 2 * m + 1] = x2 * cs + x1 * sn;
}

// ---------------- attention: one block per (h, b) ----------------
__global__ void attn_kernel(const float* __restrict__ kcache, const float* __restrict__ vcache,
                            const int* __restrict__ kidx, const int* __restrict__ vidx,
                            const float* __restrict__ mask, float* __restrict__ ctx) {
    const int h = blockIdx.x, b = blockIdx.y;
    const int tid = threadIdx.x, lane = tid & 31, warp = tid >> 5;
    __shared__ const float* kptr[KVLEN];
    __shared__ const float* vptr[KVLEN];
    __shared__ float sc[KVLEN];
    __shared__ float qs[DD];
    __shared__ float red[8];

    for (int l = tid; l < KVLEN; l += 256) {
        int ki = kidx[b * KVLEN + l];
        int mk = g_kmap[ki];
        kptr[l] = (mk >= 0) ? (g_k + mk * NEMB + h * DD)
                            : (kcache + (size_t)ki * NEMB + h * DD);
        int vi = vidx[b * KVLEN + l];
        int mv = g_vmap[vi];
        vptr[l] = (mv >= 0) ? (g_v + mv * NEMB + h * DD)
                            : (vcache + (size_t)vi * NEMB + h * DD);
    }
    qs[tid] = g_q[b * NEMB + h * DD + tid];
    __syncthreads();

    const float4* qp = reinterpret_cast<const float4*>(qs);
    float4 qa = qp[lane], qb = qp[32 + lane];
    const float* mrow = mask + b * KVLEN;
    for (int l0 = warp * 128; l0 < warp * 128 + 128; l0 += 4) {
        float dot[4];
#pragma unroll
        for (int u = 0; u < 4; ++u) {
            const float4* kr = reinterpret_cast<const float4*>(kptr[l0 + u]);
            float4 ka = kr[lane], kb = kr[32 + lane];
            dot[u] = qa.x * ka.x + qa.y * ka.y + qa.z * ka.z + qa.w * ka.w
                   + qb.x * kb.x + qb.y * kb.y + qb.z * kb.z + qb.w * kb.w;
        }
#pragma unroll
        for (int u = 0; u < 4; ++u) {
#pragma unroll
            for (int off = 16; off; off >>= 1)
                dot[u] += __shfl_xor_sync(0xffffffffu, dot[u], off);
        }
        if (lane == 0) {
#pragma unroll
            for (int u = 0; u < 4; ++u)
                sc[l0 + u] = dot[u] * 0.0625f + mrow[l0 + u];
        }
    }
    __syncthreads();

    float lm = -1e30f;
    for (int l = tid; l < KVLEN; l += 256) lm = fmaxf(lm, sc[l]);
#pragma unroll
    for (int off = 16; off; off >>= 1) lm = fmaxf(lm, __shfl_xor_sync(0xffffffffu, lm, off));
    if (lane == 0) red[warp] = lm;
    __syncthreads();
    float gm = red[0];
#pragma unroll
    for (int w = 1; w < 8; ++w) gm = fmaxf(gm, red[w]);
    float ls = 0.f;
    for (int l = tid; l < KVLEN; l += 256) {
        float e = __expf(sc[l] - gm);
        sc[l] = e;
        ls += e;
    }
#pragma unroll
    for (int off = 16; off; off >>= 1) ls += __shfl_xor_sync(0xffffffffu, ls, off);
    __syncthreads();
    if (lane == 0) red[warp] = ls;
    __syncthreads();
    float tot = red[0];
#pragma unroll
    for (int w = 1; w < 8; ++w) tot += red[w];
    float inv = 1.f / tot;

    float acc = 0.f;
#pragma unroll 8
    for (int l = 0; l < KVLEN; ++l)
        acc = fmaf(sc[l], vptr[l][tid], acc);
    ctx[b * NEMB + h * DD + tid] = acc * inv;
}

// ---------------- launch ----------------
extern "C" void kernel_launch(void* const* d_in, const int* in_sizes, int n_in,
                              void* d_out, int out_size) {
    const float* hs  = (const float*)d_in[0];
    const float* kc  = (const float*)d_in[1];
    const float* vc  = (const float*)d_in[2];
    const float* lnw = (const float*)d_in[3];
    const float* lnb = (const float*)d_in[4];
    const float* wq  = (const float*)d_in[5];
    const float* wk  = (const float*)d_in[6];
    const float* wv  = (const float*)d_in[7];
    const float* wo  = (const float*)d_in[8];
    const float* fiw = (const float*)d_in[9];
    const float* fib = (const float*)d_in[10];
    const float* fow = (const float*)d_in[11];
    const float* fob = (const float*)d_in[12];
    const float* msk = (const float*)d_in[13];
    const int* nkl   = (const int*)d_in[14];
    const int* nvl   = (const int*)d_in[15];
    const int* pki   = (const int*)d_in[16];
    const int* pvi   = (const int*)d_in[17];
    const int* pos   = (const int*)d_in[18];
    float* out = (float*)d_out;

    float *ph, *pq, *pk, *pv, *pctx, *pattn, *pm, *ppart;
    cudaGetSymbolAddress((void**)&ph,    g_h);
    cudaGetSymbolAddress((void**)&pq,    g_q);
    cudaGetSymbolAddress((void**)&pk,    g_k);
    cudaGetSymbolAddress((void**)&pv,    g_v);
    cudaGetSymbolAddress((void**)&pctx,  g_ctx);
    cudaGetSymbolAddress((void**)&pattn, g_attn);
    cudaGetSymbolAddress((void**)&pm,    g_mact);
    cudaGetSymbolAddress((void**)&ppart, g_part);

    ln_kernel<<<BB, 256>>>(hs, lnw, lnb);
    init_maps_kernel<<<NSLOTS / 256, 256>>>();

    // fused q,k,v  (K=4096, N=4096, S=32, chunk=128, z in {0,1,2})
    gemm_qkv_kernel<<<dim3(NEMB / 512, 32, 3), 128>>>(ph, wq, wk, wv, ppart, 128);
    reduce_qkv<<<dim3(BB * NEMB / 1024, 3), 256>>>(ppart, pq, pk, pv);

    rope_kernel<<<BB * HH, 32>>>(nkl, nvl, pos);

    attn_kernel<<<dim3(HH, BB), 256>>>(kc, vc, pki, pvi, msk, pctx);

    // wo
    gemm_kernel<<<dim3(NEMB / 512, 32), 128>>>(pctx, wo, ppart, NEMB, NEMB, 128);
    reduce_plain<<<BB * NEMB / 1024, 256>>>(ppart, pattn, NEMB, 32);

    // fc_in + gelu  (K=4096, N=16384, S=16, chunk=256)
    gemm_kernel<<<dim3(NINT / 512, 16), 128>>>(ph, fiw, ppart, NEMB, NINT, 256);
    reduce_bias_gelu<<<BB * NINT / 1024, 256>>>(ppart, fib, pm, NINT, 16);

    // fc_out + bias + attn + residual  (K=16384, N=4096, S=32, chunk=512)
    gemm_kernel<<<dim3(NEMB / 512, 32), 128>>>(pm, fow, ppart, NINT, NEMB, 512);
    reduce_final<<<BB * NEMB / 1024, 256>>>(ppart, fob, pattn, hs, out, NEMB, 32);
}